// round 10
// baseline (speedup 1.0000x reference)
#include <cuda_runtime.h>
#include <cuda_fp16.h>
#include <stdint.h>
#include <math.h>

#define NP 512
#define MP 512
#define DD 1024
#define H1C 512
#define H2C 256
#define NPAIR (NP*MP)
#define STRB 80   // bytes per 32-half smem row (64B data + 16B pad)

// Scratch
__device__ uint4  g_af [(size_t)16384 * 64 * 32]; // diff^2 fragment-major (512 MB)
__device__ uint4  g_h1f[(size_t)16384 * 32 * 32]; // h1 fragment-major (256 MB)
__device__ uint4  g_qf[32 * 64 * 32];             // Q fragment-major (1 MB)
__device__ __half g_w1h[H1C * DD];
__device__ __half g_w2h[H2C * H1C];
__device__ __half g_mh[NP * DD];
__device__ float  g_dpart[(size_t)NPAIR * 2];
__device__ float  g_cost[NPAIR];

union U4 { uint4 u; __half2 h[4]; };

__device__ __forceinline__ float lrelu(float x){ return x >= 0.f ? x : 0.01f*x; }
__device__ __forceinline__ uint32_t smem_u32(const void* p){
    uint32_t a;
    asm("{ .reg .u64 t; cvta.to.shared.u64 t, %1; cvt.u32.u64 %0, t; }" : "=r"(a) : "l"(p));
    return a;
}
#define CP16(dst, src) asm volatile("cp.async.cg.shared.global [%0], [%1], 16;" :: "r"(dst), "l"(src))
#define CP_COMMIT() asm volatile("cp.async.commit_group;" ::: "memory")
#define CP_WAIT2()  asm volatile("cp.async.wait_group 2;" ::: "memory")

__device__ __forceinline__ void ldmat4(uint32_t* r, uint32_t addr){
    asm volatile("ldmatrix.sync.aligned.m8n8.x4.shared.b16 {%0,%1,%2,%3}, [%4];"
        : "=r"(r[0]),"=r"(r[1]),"=r"(r[2]),"=r"(r[3]) : "r"(addr));
}
__device__ __forceinline__ void mma_f16(float* c, const uint32_t* a, const uint32_t* b){
    asm volatile("mma.sync.aligned.m16n8k16.row.col.f32.f16.f16.f32 "
        "{%0,%1,%2,%3}, {%4,%5,%6,%7}, {%8,%9}, {%0,%1,%2,%3};"
        : "+f"(c[0]),"+f"(c[1]),"+f"(c[2]),"+f"(c[3])
        : "r"(a[0]),"r"(a[1]),"r"(a[2]),"r"(a[3]), "r"(b[0]),"r"(b[1]));
}

// MMA for warp tile 32x64: A-frags in registers, B via LDSM per k-step.
__device__ __forceinline__ void mma_block32(const uint32_t a[2][2][4], uint32_t sb,
        int wn, int rA, int cAd, float acc[2][8][4]){
#pragma unroll
    for (int ks = 0; ks < 2; ks++){
        uint32_t b[8][2];
#pragma unroll
        for (int p = 0; p < 4; p++){
            uint32_t r[4];
            ldmat4(r, sb + (uint32_t)((64*wn + 16*p + rA)*STRB + (2*ks + cAd)*16));
            b[2*p][0] = r[0]; b[2*p+1][0] = r[1];
            b[2*p][1] = r[2]; b[2*p+1][1] = r[3];
        }
#pragma unroll
        for (int mt = 0; mt < 2; mt++)
#pragma unroll
            for (int nt = 0; nt < 8; nt++)
                mma_f16(acc[mt][nt], a[ks][mt], b[nt]);
    }
}

// ---------------------------------------------------------------------------
// Precompute: fp16 weights/M row-major; Q in fragment-major layout.
// ---------------------------------------------------------------------------
__global__ void k_conv(const float* __restrict__ W1, const float* __restrict__ W2,
                       const float* __restrict__ Q,  const float* __restrict__ Maug){
    const int stride = gridDim.x * blockDim.x;
    const int i0 = blockIdx.x*blockDim.x + threadIdx.x;
    for (int i = i0; i < H1C*DD; i += stride) g_w1h[i] = __float2half(W1[i]);
    for (int i = i0; i < H2C*H1C; i += stride) g_w2h[i] = __float2half(W2[i]);
    for (int i = i0; i < NP*DD;  i += stride) g_mh[i] = __float2half(Maug[i]);
    for (int f = i0; f < 32*64*32; f += stride){
        const int t = f >> 11, ks = (f >> 5) & 63, l = f & 31;
        const int r = l >> 2, c = (l & 3) * 2;
        const float* q0 = Q + (size_t)(t*16 + r)     * DD + ks*16;
        const float* q8 = Q + (size_t)(t*16 + r + 8) * DD + ks*16;
        U4 v;
        v.h[0] = __floats2half2_rn(q0[c],   q0[c+1]);
        v.h[1] = __floats2half2_rn(q8[c],   q8[c+1]);
        v.h[2] = __floats2half2_rn(q0[c+8], q0[c+9]);
        v.h[3] = __floats2half2_rn(q8[c+8], q8[c+9]);
        g_qf[f] = v.u;
    }
}

// ---------------------------------------------------------------------------
// Diff pass: g_af[(n*32+mt)*64+ks][lane] = (Qf - M[n])^2 frags; cost fused.
// Block per n (512 blocks), 8 warps; warp handles m-tiles {w, w+8, w+16, w+24}.
// ---------------------------------------------------------------------------
__global__ __launch_bounds__(256) void k_diff(){
    __shared__ __align__(16) __half msm[DD];
    const int n = blockIdx.x;
    const int tid = threadIdx.x, lane = tid & 31, warp = tid >> 5;
    if (tid < 128) ((uint4*)msm)[tid] = ((const uint4*)&g_mh[(size_t)n*DD])[tid];
    __syncthreads();

#pragma unroll 1
    for (int mi = 0; mi < 4; mi++){
        const int mt = warp + 8*mi;
        const size_t rt = (size_t)n*32 + mt;
        float c0 = 0.f, c1 = 0.f;
#pragma unroll 4
        for (int ks = 0; ks < 64; ks++){
            U4 q; q.u = g_qf[(mt*64 + ks)*32 + lane];
            const int cb = ks*16 + (lane&3)*2;
            const __half2 mlo = *(const __half2*)&msm[cb];
            const __half2 mhi = *(const __half2*)&msm[cb + 8];
            __half2 d, s0, s1, s2, s3;
            d = __hsub2(q.h[0], mlo); s0 = __hmul2(d,d);
            d = __hsub2(q.h[1], mlo); s1 = __hmul2(d,d);
            d = __hsub2(q.h[2], mhi); s2 = __hmul2(d,d);
            d = __hsub2(q.h[3], mhi); s3 = __hmul2(d,d);
            float2 f0 = __half22float2(s0), f1 = __half22float2(s1);
            float2 f2 = __half22float2(s2), f3 = __half22float2(s3);
            c0 += (f0.x + f0.y) + (f2.x + f2.y);
            c1 += (f1.x + f1.y) + (f3.x + f3.y);
            U4 v; v.h[0] = s0; v.h[1] = s1; v.h[2] = s2; v.h[3] = s3;
            g_af[(rt*64 + ks)*32 + lane] = v.u;
        }
        c0 += __shfl_xor_sync(0xffffffffu, c0, 1);
        c0 += __shfl_xor_sync(0xffffffffu, c0, 2);
        c1 += __shfl_xor_sync(0xffffffffu, c1, 1);
        c1 += __shfl_xor_sync(0xffffffffu, c1, 2);
        if ((lane & 3) == 0){
            g_cost[n*MP + mt*16 + (lane>>2)]     = c0;
            g_cost[n*MP + mt*16 + 8 + (lane>>2)] = c1;
        }
    }
}

__global__ void k_nop(){}   // filler: keep k_layer1 at ncu's profiled index 3

// ---------------------------------------------------------------------------
// Layer 1: GEMM [262144 x 512], K=1024.  CTA 128x128, 256 thr, 2 CTAs/SM.
// A-frags LDG'd from g_af (pure GEMM).  smem: B 4 x 10240 = 40960
// ---------------------------------------------------------------------------
#define L1_SMEM (4*10240)

__global__ __launch_bounds__(256,2) void k_layer1(const float* __restrict__ b1)
{
    extern __shared__ __align__(16) char smem[];
    const int tid = threadIdx.x, lane = tid & 31, wid = tid >> 5;
    const int h0 = blockIdx.x * 128;
    const int r0 = blockIdx.y * 128;
    const int wm = wid & 3, wn = wid >> 2;
    const int rA = lane & 15, cAd = lane >> 4;

    const uint32_t sbase = smem_u32(smem);
    const uint32_t sBu = sbase;

    float acc[2][8][4];
#pragma unroll
    for (int i=0;i<2;i++)
#pragma unroll
    for (int j=0;j<8;j++)
#pragma unroll
    for (int k=0;k<4;k++) acc[i][j][k] = 0.f;

    auto fillB = [&](int c){
        const uint32_t s = sBu + (uint32_t)(c & 3) * 10240;
#pragma unroll
        for (int jj = 0; jj < 2; jj++){
            const int idx = tid + 256*jj;
            const int row = idx >> 2, ch = idx & 3;
            CP16(s + (uint32_t)(row*STRB + ch*16),
                 g_w1h + (size_t)(h0 + row)*DD + c*32 + ch*8);
        }
    };

    fillB(0); CP_COMMIT();
    fillB(1); CP_COMMIT();
    fillB(2); CP_COMMIT();

    const size_t rt0 = (size_t)((r0 + 32*wm) >> 4);

    for (int c = 0; c < 32; c++){
        uint32_t afr[2][2][4];
#pragma unroll
        for (int mt = 0; mt < 2; mt++)
#pragma unroll
            for (int ks = 0; ks < 2; ks++){
                const uint4 q = g_af[((rt0 + mt)*64 + (c*2 + ks))*32 + lane];
                afr[ks][mt][0] = q.x; afr[ks][mt][1] = q.y;
                afr[ks][mt][2] = q.z; afr[ks][mt][3] = q.w;
            }
        CP_WAIT2(); __syncthreads();
        if (c + 3 < 32) fillB(c + 3);
        CP_COMMIT();
        mma_block32(afr, sBu + (uint32_t)(c & 3)*10240, wn, rA, cAd, acc);
    }

    // epilogue: bias + lrelu, store h1 in FRAGMENT-MAJOR layout
#pragma unroll
    for (int mt = 0; mt < 2; mt++){
        const size_t rt = (size_t)((r0 + 32*wm + 16*mt) >> 4);
#pragma unroll
        for (int ntp = 0; ntp < 4; ntp++){
            const int kstep = (h0 + 64*wn + 16*ntp) >> 4;
            const int col0 = h0 + 64*wn + 16*ntp + 2*(lane&3);
            const float b00 = b1[col0],   b01 = b1[col0+1];
            const float b08 = b1[col0+8], b09 = b1[col0+9];
            U4 v;
            v.h[0] = __floats2half2_rn(lrelu(acc[mt][2*ntp][0]+b00),   lrelu(acc[mt][2*ntp][1]+b01));
            v.h[1] = __floats2half2_rn(lrelu(acc[mt][2*ntp][2]+b00),   lrelu(acc[mt][2*ntp][3]+b01));
            v.h[2] = __floats2half2_rn(lrelu(acc[mt][2*ntp+1][0]+b08), lrelu(acc[mt][2*ntp+1][1]+b09));
            v.h[3] = __floats2half2_rn(lrelu(acc[mt][2*ntp+1][2]+b08), lrelu(acc[mt][2*ntp+1][3]+b09));
            g_h1f[(rt*32 + kstep)*32 + lane] = v.u;
        }
    }
}

// ---------------------------------------------------------------------------
// Layer 2+3: GEMM [262144 x 256], K=512.  CTA 128x128, 256 thr, 2 CTAs/SM.
// A-frags LDG'd from fragment-major g_h1f.  Epilogue: bias+lrelu+W3 dot.
// smem: B 4 x 10240 = 40960
// ---------------------------------------------------------------------------
#define L2_SMEM (4*10240)

__global__ __launch_bounds__(256,2) void k_layer2(
    const float* __restrict__ b2, const float* __restrict__ W3)
{
    extern __shared__ __align__(16) char smem[];
    const int tid = threadIdx.x, lane = tid & 31, wid = tid >> 5;
    const int h0 = blockIdx.x * 128;       // 2 col blocks
    const int r0 = blockIdx.y * 128;
    const int wm = wid & 3, wn = wid >> 2;
    const int rA = lane & 15, cAd = lane >> 4;

    const uint32_t sbase = smem_u32(smem);
    const uint32_t sBu = sbase;

    float acc[2][8][4];
#pragma unroll
    for (int i=0;i<2;i++)
#pragma unroll
    for (int j=0;j<8;j++)
#pragma unroll
    for (int k=0;k<4;k++) acc[i][j][k] = 0.f;

    auto fillB = [&](int c){
        const uint32_t s = sBu + (uint32_t)(c & 3) * 10240;
#pragma unroll
        for (int jj = 0; jj < 2; jj++){
            const int idx = tid + 256*jj;
            const int row = idx >> 2, ch = idx & 3;
            CP16(s + (uint32_t)(row*STRB + ch*16),
                 g_w2h + (size_t)(h0 + row)*H1C + c*32 + ch*8);
        }
    };

    fillB(0); CP_COMMIT();
    fillB(1); CP_COMMIT();
    fillB(2); CP_COMMIT();

    const size_t rt0 = (size_t)((r0 + 32*wm) >> 4);

    for (int c = 0; c < 16; c++){
        uint32_t afr[2][2][4];
#pragma unroll
        for (int mt = 0; mt < 2; mt++)
#pragma unroll
            for (int ks = 0; ks < 2; ks++){
                const uint4 q = g_h1f[((rt0 + mt)*32 + (c*2 + ks))*32 + lane];
                afr[ks][mt][0] = q.x; afr[ks][mt][1] = q.y;
                afr[ks][mt][2] = q.z; afr[ks][mt][3] = q.w;
            }
        CP_WAIT2(); __syncthreads();
        if (c + 3 < 16) fillB(c + 3);
        CP_COMMIT();
        mma_block32(afr, sBu + (uint32_t)(c & 3)*10240, wn, rA, cAd, acc);
    }

    // epilogue: bias + lrelu + W3 dot
    const int g = lane >> 2, tg = lane & 3;
    float dot[2][2];
#pragma unroll
    for (int mt=0; mt<2; mt++){ dot[mt][0]=0.f; dot[mt][1]=0.f; }
#pragma unroll
    for (int nt = 0; nt < 8; nt++){
        const int col = h0 + 64*wn + 8*nt + 2*tg;
        const float b0v = b2[col], b1v = b2[col+1];
        const float w0 = W3[col],  w1 = W3[col+1];
#pragma unroll
        for (int mt = 0; mt < 2; mt++){
            dot[mt][0] += lrelu(acc[mt][nt][0]+b0v)*w0 + lrelu(acc[mt][nt][1]+b1v)*w1;
            dot[mt][1] += lrelu(acc[mt][nt][2]+b0v)*w0 + lrelu(acc[mt][nt][3]+b1v)*w1;
        }
    }
    float* spart = (float*)smem;   // [128][2]
    __syncthreads();
#pragma unroll
    for (int mt = 0; mt < 2; mt++)
#pragma unroll
        for (int hh = 0; hh < 2; hh++){
            float v = dot[mt][hh];
            v += __shfl_xor_sync(0xffffffffu, v, 1);
            v += __shfl_xor_sync(0xffffffffu, v, 2);
            if (tg == 0) spart[(32*wm + 16*mt + 8*hh + g)*2 + wn] = v;
        }
    __syncthreads();
    if (tid < 128){
        g_dpart[(size_t)(r0 + tid)*2 + blockIdx.x] = spart[tid*2+0] + spart[tid*2+1];
    }
}

// ---------------------------------------------------------------------------
// Softmax over n (per m) + weighted reductions
// ---------------------------------------------------------------------------
__global__ __launch_bounds__(512) void k_reduce(
    const int* __restrict__ nfg_p, const float* __restrict__ b3,
    float* __restrict__ out)
{
    __shared__ float sm[512];
    const int m = blockIdx.x, n = threadIdx.x;
    const int r = n*MP + m;
    const float v = -(g_dpart[(size_t)r*2] + g_dpart[(size_t)r*2+1] + b3[0]);

    sm[n] = v; __syncthreads();
    for (int s = 256; s; s >>= 1) {
        if (n < s) sm[n] = fmaxf(sm[n], sm[n + s]);
        __syncthreads();
    }
    const float mx = sm[0]; __syncthreads();

    const float p = expf(v - mx);
    sm[n] = p; __syncthreads();
    for (int s = 256; s; s >>= 1) {
        if (n < s) sm[n] += sm[n + s];
        __syncthreads();
    }
    const float Z = sm[0]; __syncthreads();

    const float sval = g_cost[r] * (p / Z);
    sm[n] = sval; __syncthreads();
    for (int s = 256; s; s >>= 1) {
        if (n < s) sm[n] += sm[n + s];
        __syncthreads();
    }
    const float score = sm[0]; __syncthreads();

    const int nfg = *nfg_p;
    sm[n] = (n < nfg) ? sval : 0.f; __syncthreads();
    for (int s = 256; s; s >>= 1) {
        if (n < s) sm[n] += sm[n + s];
        __syncthreads();
    }
    if (n == 0) {
        out[m]      = score;
        out[MP + m] = sm[0];
    }
}

// ---------------------------------------------------------------------------
extern "C" void kernel_launch(void* const* d_in, const int* in_sizes, int n_in,
                              void* d_out, int out_size)
{
    const float* Maug = (const float*)d_in[0];
    const float* Q    = (const float*)d_in[1];
    const float* W1   = (const float*)d_in[2];
    const float* b1   = (const float*)d_in[3];
    const float* W2   = (const float*)d_in[4];
    const float* b2   = (const float*)d_in[5];
    const float* W3   = (const float*)d_in[6];
    const float* b3   = (const float*)d_in[7];
    const int*   nfg  = (const int*)d_in[8];
    float* out = (float*)d_out;

    cudaFuncSetAttribute(k_layer1, cudaFuncAttributeMaxDynamicSharedMemorySize, L1_SMEM);
    cudaFuncSetAttribute(k_layer2, cudaFuncAttributeMaxDynamicSharedMemorySize, L2_SMEM);

    k_conv  <<<512, 256>>>(W1, W2, Q, Maug);
    k_diff  <<<NP, 256>>>();
    k_nop   <<<1, 32>>>();
    k_layer1<<<dim3(H1C/128, NPAIR/128), 256, L1_SMEM>>>(b1);
    k_layer2<<<dim3(H2C/128, NPAIR/128), 256, L2_SMEM>>>(b2, W3);
    k_reduce<<<MP, 512>>>(nfg, b3, out);
}

// round 12
// speedup vs baseline: 1.1069x; 1.1069x over previous
#include <cuda_runtime.h>
#include <cuda_fp16.h>
#include <stdint.h>
#include <math.h>

#define NP 512
#define MP 512
#define DD 1024
#define H1C 512
#define H2C 256
#define NPAIR (NP*MP)
#define STRB 80   // bytes per 32-half smem row (64B data + 16B pad)

// Scratch
__device__ uint4  g_h1f[(size_t)16384 * 32 * 32]; // h1 fragment-major (256 MB)
__device__ uint4  g_qf[32 * 64 * 32];             // Q fragment-major (1 MB)
__device__ __half g_w1h[H1C * DD];
__device__ __half g_w2h[H2C * H1C];
__device__ __half g_mh[NP * DD];
__device__ float  g_dpart[(size_t)NPAIR * 2];
__device__ float  g_cost[NPAIR];

union U4 { uint4 u; __half2 h[4]; };

__device__ __forceinline__ float lrelu(float x){ return x >= 0.f ? x : 0.01f*x; }
__device__ __forceinline__ uint32_t smem_u32(const void* p){
    uint32_t a;
    asm("{ .reg .u64 t; cvta.to.shared.u64 t, %1; cvt.u32.u64 %0, t; }" : "=r"(a) : "l"(p));
    return a;
}
#define CP16(dst, src) asm volatile("cp.async.cg.shared.global [%0], [%1], 16;" :: "r"(dst), "l"(src))
#define CP_COMMIT() asm volatile("cp.async.commit_group;" ::: "memory")
#define CP_WAIT2()  asm volatile("cp.async.wait_group 2;" ::: "memory")

__device__ __forceinline__ void ldmat4(uint32_t* r, uint32_t addr){
    asm volatile("ldmatrix.sync.aligned.m8n8.x4.shared.b16 {%0,%1,%2,%3}, [%4];"
        : "=r"(r[0]),"=r"(r[1]),"=r"(r[2]),"=r"(r[3]) : "r"(addr));
}
__device__ __forceinline__ void mma_f16(float* c, const uint32_t* a, const uint32_t* b){
    asm volatile("mma.sync.aligned.m16n8k16.row.col.f32.f16.f16.f32 "
        "{%0,%1,%2,%3}, {%4,%5,%6,%7}, {%8,%9}, {%0,%1,%2,%3};"
        : "+f"(c[0]),"+f"(c[1]),"+f"(c[2]),"+f"(c[3])
        : "r"(a[0]),"r"(a[1]),"r"(a[2]),"r"(a[3]), "r"(b[0]),"r"(b[1]));
}

// MMA for warp tile 32x64: A-frags in registers, B via LDSM per k-step.
__device__ __forceinline__ void mma_block32(const uint32_t a[2][2][4], uint32_t sb,
        int wn, int rA, int cAd, float acc[2][8][4]){
#pragma unroll
    for (int ks = 0; ks < 2; ks++){
        uint32_t b[8][2];
#pragma unroll
        for (int p = 0; p < 4; p++){
            uint32_t r[4];
            ldmat4(r, sb + (uint32_t)((64*wn + 16*p + rA)*STRB + (2*ks + cAd)*16));
            b[2*p][0] = r[0]; b[2*p+1][0] = r[1];
            b[2*p][1] = r[2]; b[2*p+1][1] = r[3];
        }
#pragma unroll
        for (int mt = 0; mt < 2; mt++)
#pragma unroll
            for (int nt = 0; nt < 8; nt++)
                mma_f16(acc[mt][nt], a[ks][mt], b[nt]);
    }
}

// ---------------------------------------------------------------------------
// Precompute: fp16 weights/M row-major; Q in fragment-major layout.
// ---------------------------------------------------------------------------
__global__ void k_conv(const float* __restrict__ W1, const float* __restrict__ W2,
                       const float* __restrict__ Q,  const float* __restrict__ Maug){
    const int stride = gridDim.x * blockDim.x;
    const int i0 = blockIdx.x*blockDim.x + threadIdx.x;
    for (int i = i0; i < H1C*DD; i += stride) g_w1h[i] = __float2half(W1[i]);
    for (int i = i0; i < H2C*H1C; i += stride) g_w2h[i] = __float2half(W2[i]);
    for (int i = i0; i < NP*DD;  i += stride) g_mh[i] = __float2half(Maug[i]);
    for (int f = i0; f < 32*64*32; f += stride){
        const int t = f >> 11, ks = (f >> 5) & 63, l = f & 31;
        const int r = l >> 2, c = (l & 3) * 2;
        const float* q0 = Q + (size_t)(t*16 + r)     * DD + ks*16;
        const float* q8 = Q + (size_t)(t*16 + r + 8) * DD + ks*16;
        U4 v;
        v.h[0] = __floats2half2_rn(q0[c],   q0[c+1]);
        v.h[1] = __floats2half2_rn(q8[c],   q8[c+1]);
        v.h[2] = __floats2half2_rn(q0[c+8], q0[c+9]);
        v.h[3] = __floats2half2_rn(q8[c+8], q8[c+9]);
        g_qf[f] = v.u;
    }
}

__global__ void k_nop(){}   // fillers: keep k_layer1 at ncu's profiled index 3

// ---------------------------------------------------------------------------
// Layer 1: GEMM [262144 x 512], K=1024.  CTA 128x128, 256 thr, 2 CTAs/SM.
// A-frags in registers from Qf + M(smem).  6-stage B ring, barrier per
// 2-chunk window (de-convoy).  smem: B 6 x 10240 + Mrow 2048 = 63488
// ---------------------------------------------------------------------------
#define L1_SMEM (6*10240 + 2048)
#define MOFF    (6*10240)

__global__ __launch_bounds__(256,2) void k_layer1(const float* __restrict__ b1)
{
    extern __shared__ __align__(16) char smem[];
    const int tid = threadIdx.x, lane = tid & 31, wid = tid >> 5;
    const int h0 = blockIdx.x * 128;
    const int r0 = blockIdx.y * 128;
    const int n  = r0 >> 9;
    const int m0 = r0 & 511;
    const int wm = wid & 3, wn = wid >> 2;
    const int rA = lane & 15, cAd = lane >> 4;
    const bool do_cost = (blockIdx.x == 0) && (wn == 0);

    const uint32_t sbase = smem_u32(smem);
    const uint32_t sBu = sbase;

    // M row -> smem (2 KB = 128 uint4)
    if (tid < 128)
        ((uint4*)(smem + MOFF))[tid] = ((const uint4*)&g_mh[(size_t)n*DD])[tid];

    float acc[2][8][4];
#pragma unroll
    for (int i=0;i<2;i++)
#pragma unroll
    for (int j=0;j<8;j++)
#pragma unroll
    for (int k=0;k<4;k++) acc[i][j][k] = 0.f;
    float creg[2][2];
#pragma unroll
    for (int i=0;i<2;i++){ creg[i][0]=0.f; creg[i][1]=0.f; }

    auto fillB = [&](int c){
        const uint32_t s = sBu + (uint32_t)(c % 6) * 10240;
#pragma unroll
        for (int jj = 0; jj < 2; jj++){
            const int idx = tid + 256*jj;
            const int row = idx >> 2, ch = idx & 3;
            CP16(s + (uint32_t)(row*STRB + ch*16),
                 g_w1h + (size_t)(h0 + row)*DD + c*32 + ch*8);
        }
    };

    const int qt0 = (m0 + 32*wm) >> 4;   // Qf tile base for this warp

    auto doChunk = [&](int cc){
        uint4 qf[4];
#pragma unroll
        for (int mt = 0; mt < 2; mt++)
#pragma unroll
            for (int ks = 0; ks < 2; ks++)
                qf[mt*2+ks] = g_qf[((qt0 + mt)*64 + (cc*2 + ks))*32 + lane];

        uint32_t afr[2][2][4];
#pragma unroll
        for (int ks = 0; ks < 2; ks++){
            const int cb = (cc*32 + ks*16 + (lane&3)*2)*2;
            const __half2 mlo = *(const __half2*)(smem + MOFF + cb);
            const __half2 mhi = *(const __half2*)(smem + MOFF + cb + 16);
#pragma unroll
            for (int mt = 0; mt < 2; mt++){
                U4 q; q.u = qf[mt*2+ks];
                __half2 d, s0, s1, s2, s3;
                d = __hsub2(q.h[0], mlo); s0 = __hmul2(d,d);
                d = __hsub2(q.h[1], mlo); s1 = __hmul2(d,d);
                d = __hsub2(q.h[2], mhi); s2 = __hmul2(d,d);
                d = __hsub2(q.h[3], mhi); s3 = __hmul2(d,d);
                afr[ks][mt][0] = *(uint32_t*)&s0;
                afr[ks][mt][1] = *(uint32_t*)&s1;
                afr[ks][mt][2] = *(uint32_t*)&s2;
                afr[ks][mt][3] = *(uint32_t*)&s3;
                if (do_cost){
                    float2 f0 = __half22float2(s0), f1 = __half22float2(s1);
                    float2 f2 = __half22float2(s2), f3 = __half22float2(s3);
                    creg[mt][0] += (f0.x + f0.y) + (f2.x + f2.y);
                    creg[mt][1] += (f1.x + f1.y) + (f3.x + f3.y);
                }
            }
        }
        mma_block32(afr, sBu + (uint32_t)(cc % 6)*10240, wn, rA, cAd, acc);
    };

    fillB(0); CP_COMMIT();
    fillB(1); CP_COMMIT();
    fillB(2); CP_COMMIT();
    fillB(3); CP_COMMIT();

    for (int c = 0; c < 32; c += 2){
        CP_WAIT2(); __syncthreads();          // stages c, c+1 ready CTA-wide
        if (c + 4 < 32) fillB(c + 4);
        CP_COMMIT();                          // unconditional: uniform group count
        if (c + 5 < 32) fillB(c + 5);
        CP_COMMIT();
        doChunk(c);
        doChunk(c + 1);
    }

    // fused cost: reduce over the 4 lanes sharing each row
    if (do_cost){
#pragma unroll
        for (int mt = 0; mt < 2; mt++)
#pragma unroll
            for (int hh = 0; hh < 2; hh++){
                float v = creg[mt][hh];
                v += __shfl_xor_sync(0xffffffffu, v, 1);
                v += __shfl_xor_sync(0xffffffffu, v, 2);
                if ((lane & 3) == 0)
                    g_cost[n*MP + m0 + 32*wm + 16*mt + 8*hh + (lane>>2)] = v;
            }
    }

    // epilogue: bias + lrelu, store h1 in FRAGMENT-MAJOR layout
#pragma unroll
    for (int mt = 0; mt < 2; mt++){
        const size_t rt = (size_t)((r0 + 32*wm + 16*mt) >> 4);
#pragma unroll
        for (int ntp = 0; ntp < 4; ntp++){
            const int kstep = (h0 + 64*wn + 16*ntp) >> 4;
            const int col0 = h0 + 64*wn + 16*ntp + 2*(lane&3);
            const float b00 = b1[col0],   b01 = b1[col0+1];
            const float b08 = b1[col0+8], b09 = b1[col0+9];
            U4 v;
            v.h[0] = __floats2half2_rn(lrelu(acc[mt][2*ntp][0]+b00),   lrelu(acc[mt][2*ntp][1]+b01));
            v.h[1] = __floats2half2_rn(lrelu(acc[mt][2*ntp][2]+b00),   lrelu(acc[mt][2*ntp][3]+b01));
            v.h[2] = __floats2half2_rn(lrelu(acc[mt][2*ntp+1][0]+b08), lrelu(acc[mt][2*ntp+1][1]+b09));
            v.h[3] = __floats2half2_rn(lrelu(acc[mt][2*ntp+1][2]+b08), lrelu(acc[mt][2*ntp+1][3]+b09));
            g_h1f[(rt*32 + kstep)*32 + lane] = v.u;
        }
    }
}

// ---------------------------------------------------------------------------
// Layer 2+3: GEMM [262144 x 256], K=512.  CTA 128x128, 256 thr, 2 CTAs/SM.
// A-frags LDG'd from fragment-major g_h1f.  6-stage ring, 2-chunk windows.
// Epilogue: bias + lrelu + W3 dot.  smem: B 6 x 10240 = 61440
// ---------------------------------------------------------------------------
#define L2_SMEM (6*10240)

__global__ __launch_bounds__(256,2) void k_layer2(
    const float* __restrict__ b2, const float* __restrict__ W3)
{
    extern __shared__ __align__(16) char smem[];
    const int tid = threadIdx.x, lane = tid & 31, wid = tid >> 5;
    const int h0 = blockIdx.x * 128;       // 2 col blocks
    const int r0 = blockIdx.y * 128;
    const int wm = wid & 3, wn = wid >> 2;
    const int rA = lane & 15, cAd = lane >> 4;

    const uint32_t sbase = smem_u32(smem);
    const uint32_t sBu = sbase;

    float acc[2][8][4];
#pragma unroll
    for (int i=0;i<2;i++)
#pragma unroll
    for (int j=0;j<8;j++)
#pragma unroll
    for (int k=0;k<4;k++) acc[i][j][k] = 0.f;

    auto fillB = [&](int c){
        const uint32_t s = sBu + (uint32_t)(c % 6) * 10240;
#pragma unroll
        for (int jj = 0; jj < 2; jj++){
            const int idx = tid + 256*jj;
            const int row = idx >> 2, ch = idx & 3;
            CP16(s + (uint32_t)(row*STRB + ch*16),
                 g_w2h + (size_t)(h0 + row)*H1C + c*32 + ch*8);
        }
    };

    const size_t rt0 = (size_t)((r0 + 32*wm) >> 4);

    auto doChunk = [&](int cc){
        uint32_t afr[2][2][4];
#pragma unroll
        for (int mt = 0; mt < 2; mt++)
#pragma unroll
            for (int ks = 0; ks < 2; ks++){
                const uint4 q = g_h1f[((rt0 + mt)*32 + (cc*2 + ks))*32 + lane];
                afr[ks][mt][0] = q.x; afr[ks][mt][1] = q.y;
                afr[ks][mt][2] = q.z; afr[ks][mt][3] = q.w;
            }
        mma_block32(afr, sBu + (uint32_t)(cc % 6)*10240, wn, rA, cAd, acc);
    };

    fillB(0); CP_COMMIT();
    fillB(1); CP_COMMIT();
    fillB(2); CP_COMMIT();
    fillB(3); CP_COMMIT();

    for (int c = 0; c < 16; c += 2){
        CP_WAIT2(); __syncthreads();
        if (c + 4 < 16) fillB(c + 4);
        CP_COMMIT();
        if (c + 5 < 16) fillB(c + 5);
        CP_COMMIT();
        doChunk(c);
        doChunk(c + 1);
    }

    // epilogue: bias + lrelu + W3 dot
    const int g = lane >> 2, tg = lane & 3;
    float dot[2][2];
#pragma unroll
    for (int mt=0; mt<2; mt++){ dot[mt][0]=0.f; dot[mt][1]=0.f; }
#pragma unroll
    for (int nt = 0; nt < 8; nt++){
        const int col = h0 + 64*wn + 8*nt + 2*tg;
        const float b0v = b2[col], b1v = b2[col+1];
        const float w0 = W3[col],  w1 = W3[col+1];
#pragma unroll
        for (int mt = 0; mt < 2; mt++){
            dot[mt][0] += lrelu(acc[mt][nt][0]+b0v)*w0 + lrelu(acc[mt][nt][1]+b1v)*w1;
            dot[mt][1] += lrelu(acc[mt][nt][2]+b0v)*w0 + lrelu(acc[mt][nt][3]+b1v)*w1;
        }
    }
    float* spart = (float*)smem;   // [128][2]
    __syncthreads();
#pragma unroll
    for (int mt = 0; mt < 2; mt++)
#pragma unroll
        for (int hh = 0; hh < 2; hh++){
            float v = dot[mt][hh];
            v += __shfl_xor_sync(0xffffffffu, v, 1);
            v += __shfl_xor_sync(0xffffffffu, v, 2);
            if (tg == 0) spart[(32*wm + 16*mt + 8*hh + g)*2 + wn] = v;
        }
    __syncthreads();
    if (tid < 128){
        g_dpart[(size_t)(r0 + tid)*2 + blockIdx.x] = spart[tid*2+0] + spart[tid*2+1];
    }
}

// ---------------------------------------------------------------------------
// Softmax over n (per m) + weighted reductions
// ---------------------------------------------------------------------------
__global__ __launch_bounds__(512) void k_reduce(
    const int* __restrict__ nfg_p, const float* __restrict__ b3,
    float* __restrict__ out)
{
    __shared__ float sm[512];
    const int m = blockIdx.x, n = threadIdx.x;
    const int r = n*MP + m;
    const float v = -(g_dpart[(size_t)r*2] + g_dpart[(size_t)r*2+1] + b3[0]);

    sm[n] = v; __syncthreads();
    for (int s = 256; s; s >>= 1) {
        if (n < s) sm[n] = fmaxf(sm[n], sm[n + s]);
        __syncthreads();
    }
    const float mx = sm[0]; __syncthreads();

    const float p = expf(v - mx);
    sm[n] = p; __syncthreads();
    for (int s = 256; s; s >>= 1) {
        if (n < s) sm[n] += sm[n + s];
        __syncthreads();
    }
    const float Z = sm[0]; __syncthreads();

    const float sval = g_cost[r] * (p / Z);
    sm[n] = sval; __syncthreads();
    for (int s = 256; s; s >>= 1) {
        if (n < s) sm[n] += sm[n + s];
        __syncthreads();
    }
    const float score = sm[0]; __syncthreads();

    const int nfg = *nfg_p;
    sm[n] = (n < nfg) ? sval : 0.f; __syncthreads();
    for (int s = 256; s; s >>= 1) {
        if (n < s) sm[n] += sm[n + s];
        __syncthreads();
    }
    if (n == 0) {
        out[m]      = score;
        out[MP + m] = sm[0];
    }
}

// ---------------------------------------------------------------------------
extern "C" void kernel_launch(void* const* d_in, const int* in_sizes, int n_in,
                              void* d_out, int out_size)
{
    const float* Maug = (const float*)d_in[0];
    const float* Q    = (const float*)d_in[1];
    const float* W1   = (const float*)d_in[2];
    const float* b1   = (const float*)d_in[3];
    const float* W2   = (const float*)d_in[4];
    const float* b2   = (const float*)d_in[5];
    const float* W3   = (const float*)d_in[6];
    const float* b3   = (const float*)d_in[7];
    const int*   nfg  = (const int*)d_in[8];
    float* out = (float*)d_out;

    cudaFuncSetAttribute(k_layer1, cudaFuncAttributeMaxDynamicSharedMemorySize, L1_SMEM);
    cudaFuncSetAttribute(k_layer2, cudaFuncAttributeMaxDynamicSharedMemorySize, L2_SMEM);

    k_conv  <<<512, 256>>>(W1, W2, Q, Maug);
    k_nop   <<<1, 32>>>();
    k_nop   <<<1, 32>>>();
    k_layer1<<<dim3(H1C/128, NPAIR/128), 256, L1_SMEM>>>(b1);
    k_layer2<<<dim3(H2C/128, NPAIR/128), 256, L2_SMEM>>>(b2, W3);
    k_reduce<<<MP, 512>>>(nfg, b3, out);
}